// round 1
// baseline (speedup 1.0000x reference)
#include <cuda_runtime.h>
#include <cstdint>

#define NPTS    8192
#define DIMS    3
#define THREADS 256
#define IPT     4                     // i-points per thread (2 packed f32x2 chains)
#define TILE_I  (THREADS * IPT)       // 1024 -> 8 i-tiles per (batch, dir)
#define JCHUNK  4096                  // j per smem pass (2 passes)
#define SMEM_BYTES (JCHUNK * 32)      // duplicated layout: 32 B per j = 128 KB

__device__ float g_partials[1024];

// ---- packed f32x2 helpers (sm_100+ PTX) ------------------------------------
__device__ __forceinline__ unsigned long long fma2(unsigned long long a,
                                                   unsigned long long b,
                                                   unsigned long long c) {
    unsigned long long d;
    asm("fma.rn.f32x2 %0, %1, %2, %3;" : "=l"(d) : "l"(a), "l"(b), "l"(c));
    return d;
}
__device__ __forceinline__ unsigned long long pack2(float lo, float hi) {
    unsigned long long d;
    unsigned int l = __float_as_uint(lo), h = __float_as_uint(hi);
    asm("mov.b64 %0, {%1, %2};" : "=l"(d) : "r"(l), "r"(h));
    return d;
}
__device__ __forceinline__ void unpack2(unsigned long long v, float& lo, float& hi) {
    unsigned int l, h;
    asm("mov.b64 {%0, %1}, %2;" : "=r"(l), "=r"(h) : "l"(v));
    lo = __uint_as_float(l);
    hi = __uint_as_float(h);
}

// ---- main kernel: one block = (i-tile, batch, direction) -------------------
__global__ __launch_bounds__(THREADS, 1)
void chamfer_main(const float* __restrict__ preds,
                  const float* __restrict__ gts) {
    extern __shared__ unsigned long long sy[];  // [JCHUNK * 4] ull per j: y0d,y1d,y2d,ryd

    const int b   = blockIdx.y;
    const int dir = blockIdx.z;
    const float* X = (dir == 0) ? preds : gts;   // query points
    const float* Y = (dir == 0) ? gts   : preds; // reference points
    const float* Xb = X + (size_t)b * DIMS * NPTS;
    const float* Yb = Y + (size_t)b * DIMS * NPTS;

    const int i0 = blockIdx.x * TILE_I;
    const int t  = threadIdx.x;

    // Load IPT query points per thread (coalesced), compute rx.
    float x0[IPT], x1[IPT], x2[IPT], rx[IPT];
#pragma unroll
    for (int k = 0; k < IPT; k++) {
        int i = i0 + k * THREADS + t;
        x0[k] = Xb[i];
        x1[k] = Xb[NPTS + i];
        x2[k] = Xb[2 * NPTS + i];
        rx[k] = x0[k] * x0[k] + x1[k] * x1[k] + x2[k] * x2[k];
    }

    // Pack pairs of i-points into f32x2 lanes (pairs (0,1) and (2,3)).
    unsigned long long x0d[IPT / 2], x1d[IPT / 2], x2d[IPT / 2];
#pragma unroll
    for (int c = 0; c < IPT / 2; c++) {
        x0d[c] = pack2(x0[2 * c], x0[2 * c + 1]);
        x1d[c] = pack2(x1[2 * c], x1[2 * c + 1]);
        x2d[c] = pack2(x2[2 * c], x2[2 * c + 1]);
    }

    float mn[IPT];
#pragma unroll
    for (int k = 0; k < IPT; k++) mn[k] = 3.4e38f;

    for (int pass = 0; pass < NPTS / JCHUNK; pass++) {
        const int jbase = pass * JCHUNK;
        __syncthreads();
        // Fill smem: per j, duplicated packed layout {-2y0,-2y0,-2y1,-2y1,-2y2,-2y2,ry,ry}
        for (int j = t; j < JCHUNK; j += THREADS) {
            float y0 = Yb[jbase + j];
            float y1 = Yb[NPTS + jbase + j];
            float y2 = Yb[2 * NPTS + jbase + j];
            float ry = y0 * y0 + y1 * y1 + y2 * y2;
            unsigned long long* p = &sy[(size_t)j * 4];
            p[0] = pack2(-2.f * y0, -2.f * y0);
            p[1] = pack2(-2.f * y1, -2.f * y1);
            p[2] = pack2(-2.f * y2, -2.f * y2);
            p[3] = pack2(ry, ry);
        }
        __syncthreads();

#pragma unroll 4
        for (int j = 0; j < JCHUNK; j++) {
            // Two broadcast LDS.128: all lanes read the same j.
            ulonglong2 ya = *reinterpret_cast<const ulonglong2*>(&sy[(size_t)j * 4]);
            ulonglong2 yb = *reinterpret_cast<const ulonglong2*>(&sy[(size_t)j * 4 + 2]);
#pragma unroll
            for (int c = 0; c < IPT / 2; c++) {
                // acc = ry - 2*(x.y)   (rx folded in after the loop)
                unsigned long long acc = fma2(x2d[c], yb.x, yb.y);
                acc = fma2(x1d[c], ya.y, acc);
                acc = fma2(x0d[c], ya.x, acc);
                float lo, hi;
                unpack2(acc, lo, hi);
                mn[2 * c]     = fminf(mn[2 * c], lo);
                mn[2 * c + 1] = fminf(mn[2 * c + 1], hi);
            }
        }
    }

    // Per-thread partial: sum_k (min_j(ry-2dot) + rx)
    float s = 0.f;
#pragma unroll
    for (int k = 0; k < IPT; k++) s += mn[k] + rx[k];

    // Deterministic block tree-reduction (reuse smem).
    __syncthreads();
    float* sred = reinterpret_cast<float*>(sy);
    sred[t] = s;
    __syncthreads();
    for (int stride = THREADS / 2; stride > 0; stride >>= 1) {
        if (t < stride) sred[t] += sred[t + stride];
        __syncthreads();
    }
    if (t == 0) {
        int bid = (blockIdx.z * gridDim.y + blockIdx.y) * gridDim.x + blockIdx.x;
        g_partials[bid] = sred[0];
    }
}

// ---- fixed-order finalize: deterministic scalar sum -------------------------
__global__ void chamfer_finalize(float* __restrict__ out, int nparts) {
    __shared__ float sred[256];
    float s = 0.f;
    for (int i = threadIdx.x; i < nparts; i += 256) s += g_partials[i];
    sred[threadIdx.x] = s;
    __syncthreads();
    for (int stride = 128; stride > 0; stride >>= 1) {
        if (threadIdx.x < stride) sred[threadIdx.x] += sred[threadIdx.x + stride];
        __syncthreads();
    }
    if (threadIdx.x == 0) out[0] = sred[0];
}

extern "C" void kernel_launch(void* const* d_in, const int* in_sizes, int n_in,
                              void* d_out, int out_size) {
    const float* preds = (const float*)d_in[0];
    const float* gts   = (const float*)d_in[1];
    float* out = (float*)d_out;

    const int B = in_sizes[0] / (DIMS * NPTS);  // 8 for this problem

    static bool attr_set = false;
    if (!attr_set) {
        cudaFuncSetAttribute(chamfer_main,
                             cudaFuncAttributeMaxDynamicSharedMemorySize,
                             SMEM_BYTES);
        attr_set = true;
    }

    dim3 grid(NPTS / TILE_I, B, 2);  // (8, 8, 2) = 128 blocks, one wave
    chamfer_main<<<grid, THREADS, SMEM_BYTES>>>(preds, gts);

    int nparts = (NPTS / TILE_I) * B * 2;
    chamfer_finalize<<<1, 256>>>(out, nparts);
}